// round 4
// baseline (speedup 1.0000x reference)
#include <cuda_runtime.h>
#include <math.h>
#include <float.h>

#define BB 32
#define QQ 900
#define MM 128
#define KC 80
#define KP1 81
#define INFF __int_as_float(0x7f800000)

// scratch (no allocations allowed -> __device__ globals)
__device__ float g_costT[BB * MM * QQ];     // 14.7 MB, TRANSPOSED [b][m][q]
__device__ float g_lse[BB * QQ];
__device__ float g_acc[3];
__device__ unsigned g_done;

// monotone float->uint mapping (preserves < ordering)
__device__ __forceinline__ unsigned ford(float f) {
    unsigned u = __float_as_uint(f);
    return u ^ ((u >> 31) ? 0xffffffffu : 0x80000000u);
}

// ---------------- kernel A: fused softmax + transposed cost matrix -------------
// grid (8, B), block 128. Each block owns a 128-q tile of one image.
__global__ void __launch_bounds__(128) k_costT(
    const float* __restrict__ logits,
    const float* __restrict__ pboxes,
    const float* __restrict__ tboxes,
    const float* __restrict__ sizes,
    const int*   __restrict__ labels) {
    int b = blockIdx.y, tid = threadIdx.x;
    int q0 = blockIdx.x * 128;
    int q = q0 + tid;
    __shared__ float sprob[128 * KP1];       // 41.5 KB
    __shared__ float tn0[MM], tn1[MM], tn2[MM], tn3[MM], tc[MM], ts[MM];
    __shared__ int   tl[MM];

    if (b == 0 && blockIdx.x == 0 && tid < 4) {
        if (tid < 3) g_acc[tid] = 0.f; else g_done = 0u;
    }

    float H = sizes[b * 2 + 0], W = sizes[b * 2 + 1];
    {   // tid doubles as target index m
        const float* tb = tboxes + ((size_t)b * MM + tid) * 5;
        tn0[tid] = tb[0] / W; tn1[tid] = tb[1] / H;
        tn2[tid] = tb[2] / W; tn3[tid] = tb[3] / H;
        float sn, cs; sincosf(tb[4], &sn, &cs);
        tc[tid] = cs; ts[tid] = sn;
        tl[tid] = labels[b * MM + tid];
    }
    // coalesced copy of this tile's logits into smem
    int nrow = min(128, QQ - q0);
    int tot = nrow * KP1;
    const float* lg0 = logits + ((size_t)b * QQ + q0) * KP1;
    for (int i = tid; i < tot; i += 128) sprob[i] = lg0[i];
    __syncthreads();

    bool valid = q < QQ;
    if (valid) {
        float* r = sprob + tid * KP1;        // stride 81: bank-conflict-free
        float mx = -FLT_MAX;
#pragma unroll 9
        for (int k = 0; k < KP1; k++) mx = fmaxf(mx, r[k]);
        float s = 0.f;
#pragma unroll 9
        for (int k = 0; k < KP1; k++) { float e = __expf(r[k] - mx); r[k] = e; s += e; }
        float inv = 1.f / s;
#pragma unroll 9
        for (int k = 0; k < KP1; k++) r[k] *= inv;
        g_lse[b * QQ + q] = mx + __logf(s);
    }
    __syncthreads();
    if (!valid) return;

    const float* pb = pboxes + ((size_t)b * QQ + q) * 5;
    float p0 = pb[0], p1 = pb[1], p2 = pb[2], p3 = pb[3];
    float ps, pc; sincosf(pb[4], &ps, &pc);
    const float* r = sprob + tid * KP1;
    float* outb = g_costT + (size_t)b * MM * QQ + q;
#pragma unroll 4
    for (int m = 0; m < MM; m++) {
        float prob = r[tl[m]];
        float l1 = fabsf(p0 - tn0[m]) + fabsf(p1 - tn1[m]) +
                   fabsf(p2 - tn2[m]) + fabsf(p3 - tn3[m]);
        float cosd = pc * tc[m] + ps * ts[m];            // cos(p4 - t4)
        outb[(size_t)m * QQ] = -2.f * prob + 5.f * l1 + 2.f * (1.f - cosd);
    }
}

// ---------------- kernel B: match (warp0, register state) + fused losses -------
__global__ void __launch_bounds__(256, 1) k_match_loss(
    const float* __restrict__ logits,
    const float* __restrict__ pboxes,
    const float* __restrict__ tboxes,
    const float* __restrict__ sizes,
    const int*   __restrict__ labels,
    float* __restrict__ out) {
    int b = blockIdx.x, tid = threadIdx.x;
    int lane = tid & 31, wid = tid >> 5;
    __shared__ unsigned cum[MM];       // ford-encoded column minima
    __shared__ int      carg[MM];
    __shared__ float    rmask[QQ];     // 0 = free row, +INF = used
    __shared__ short    sq[MM], sm[MM];
    __shared__ int      mlab[QQ];
    __shared__ float    buf[256];
    const float* C = g_costT + (size_t)b * MM * QQ;

    for (int q = tid; q < QQ; q += 256) rmask[q] = 0.f;

    // ---- init: one warp per column (coalesced column scan) ----
    for (int m = wid; m < MM; m += 8) {
        const float* col = C + (size_t)m * QQ;
        float bv = INFF; int bq = -1;
#pragma unroll 7
        for (int j = 0; j < 28; j++) {
            int q = lane + 32 * j;
            float v = col[q];
            if (v < bv) { bv = v; bq = q; }            // ascending q keeps smallest
        }
        { int q = lane + 896; if (q < QQ) { float v = col[q]; if (v < bv) { bv = v; bq = q; } } }
        unsigned u = ford(bv);
        unsigned umin = __reduce_min_sync(0xffffffffu, u);
        unsigned qsel = (u == umin) ? (unsigned)bq : 0xffffffffu;
        unsigned qmin = __reduce_min_sync(0xffffffffu, qsel);
        if (lane == 0) { cum[m] = umin; carg[m] = (int)qmin; }
    }
    __syncthreads();

    // ---- matching loop: warp0 only, state in registers ----
    if (wid == 0) {
        unsigned u[4]; int qa[4];
#pragma unroll
        for (int g = 0; g < 4; g++) { u[g] = cum[lane + 32 * g]; qa[g] = carg[lane + 32 * g]; }

        for (int it = 0; it < MM; it++) {
            // global argmin over 128 (value, q, m) keys
            unsigned long long key = ~0ull;
#pragma unroll
            for (int g = 0; g < 4; g++) {
                unsigned long long k2 = ((unsigned long long)u[g] << 17)
                                      | ((unsigned)qa[g] << 7) | (unsigned)(lane + 32 * g);
                if (k2 < key) key = k2;
            }
            unsigned hi = (unsigned)(key >> 17);
            unsigned himin = __reduce_min_sync(0xffffffffu, hi);
            unsigned lo = (hi == himin) ? (unsigned)(key & 0x1ffffu) : 0xffffffffu;
            unsigned lomin = __reduce_min_sync(0xffffffffu, lo);
            int qs = (int)(lomin >> 7);
            int ms = (int)(lomin & 127u);

            if (lane == 0) { sq[it] = (short)qs; sm[it] = (short)ms; rmask[qs] = INFF; }
            if (lane == (ms & 31)) { u[ms >> 5] = 0xffffffffu; qa[ms >> 5] = 0x3ff; }
            __syncwarp();
            if (it == MM - 1) break;

            // rescan columns whose cached argmin row was just consumed
#pragma unroll
            for (int g = 0; g < 4; g++) {
                unsigned bal = __ballot_sync(0xffffffffu,
                                             qa[g] == qs && u[g] != 0xffffffffu);
                while (bal) {
                    int c = __ffs(bal) - 1; bal &= bal - 1;
                    int mr = c + 32 * g;
                    const float* col = C + (size_t)mr * QQ;
                    float nv = INFF; int nq = -1;
#pragma unroll 7
                    for (int j = 0; j < 28; j++) {
                        int q2 = lane + 32 * j;
                        float v = col[q2] + rmask[q2];
                        if (v < nv) { nv = v; nq = q2; }
                    }
                    { int q2 = lane + 896; if (q2 < QQ) { float v = col[q2] + rmask[q2]; if (v < nv) { nv = v; nq = q2; } } }
                    unsigned uu = ford(nv);
                    unsigned um = __reduce_min_sync(0xffffffffu, uu);
                    unsigned qq = (uu == um) ? (unsigned)nq : 0xffffffffu;
                    unsigned qmn = __reduce_min_sync(0xffffffffu, qq);
                    if (lane == c) { u[g] = um; qa[g] = (int)qmn; }
                    __syncwarp();
                }
            }
        }
    }
    __syncthreads();

    // ---- fused per-image losses (all 256 threads) ----
    for (int q = tid; q < QQ; q += 256) mlab[q] = -1;
    __syncthreads();
    if (tid < MM) mlab[sq[tid]] = labels[b * MM + sm[tid]];
    __syncthreads();

    float num = 0.f;
    for (int q = tid; q < QQ; q += 256) {
        int c = mlab[q];
        float w;
        if (c < 0) { c = KC; w = 0.1f; } else w = 1.f;
        int row = b * QQ + q;
        num += w * (g_lse[row] - logits[(size_t)row * KP1 + c]);
    }

    float sb = 0.f, sa = 0.f;
    if (tid < MM) {
        int q = sq[tid], m = sm[tid];
        float H = sizes[b * 2 + 0], W = sizes[b * 2 + 1];
        const float* pb = pboxes + ((size_t)b * QQ + q) * 5;
        const float* tb = tboxes + ((size_t)b * MM + m) * 5;
        sb = fabsf(pb[0] - tb[0] / W) + fabsf(pb[1] - tb[1] / H) +
             fabsf(pb[2] - tb[2] / W) + fabsf(pb[3] - tb[3] / H);
        sa = 1.f - cosf(pb[4] - tb[4]);
    }

    // block reductions
    buf[tid] = num; __syncthreads();
    for (int s = 128; s > 0; s >>= 1) { if (tid < s) buf[tid] += buf[tid + s]; __syncthreads(); }
    float numt = buf[0]; __syncthreads();
    buf[tid] = sb; __syncthreads();
    for (int s = 128; s > 0; s >>= 1) { if (tid < s) buf[tid] += buf[tid + s]; __syncthreads(); }
    float sbt = buf[0]; __syncthreads();
    buf[tid] = sa; __syncthreads();
    for (int s = 128; s > 0; s >>= 1) { if (tid < s) buf[tid] += buf[tid + s]; __syncthreads(); }
    float sat = buf[0];

    if (tid == 0) {
        atomicAdd(&g_acc[0], numt);
        atomicAdd(&g_acc[1], sbt);
        atomicAdd(&g_acc[2], sat);
        __threadfence();
        unsigned done = atomicAdd(&g_done, 1u);
        if (done == BB - 1) {
            const float den = 0.1f * (QQ - MM) + (float)MM;   // 205.2 per image
            float lc = g_acc[0] / (den * BB);
            float lb = g_acc[1] * 5.f / (float)(MM * 4 * BB);
            float la = g_acc[2] * 2.f / (float)(MM * BB);
            out[0] = lc;
            out[1] = lb;
            out[2] = la;
            out[3] = lc + lb + la;
        }
    }
}

extern "C" void kernel_launch(void* const* d_in, const int* in_sizes, int n_in,
                              void* d_out, int out_size) {
    const float* logits = (const float*)d_in[0];   // [B,Q,81]
    const float* pboxes = (const float*)d_in[1];   // [B,Q,5]
    const float* tboxes = (const float*)d_in[2];   // [B,M,5]
    const float* sizes  = (const float*)d_in[3];   // [B,2]
    const int*   labels = (const int*)d_in[4];     // [B,M]
    float* out = (float*)d_out;

    dim3 gc((QQ + 127) / 128, BB);
    k_costT<<<gc, 128>>>(logits, pboxes, tboxes, sizes, labels);
    k_match_loss<<<BB, 256>>>(logits, pboxes, tboxes, sizes, labels, out);
}

// round 5
// speedup vs baseline: 1.2409x; 1.2409x over previous
#include <cuda_runtime.h>
#include <math.h>
#include <float.h>

#define BB 32
#define QQ 900
#define MM 128
#define KC 80
#define KP1 81
#define NT 8                       // q-tiles per image (8*128 >= 900)
#define INFF __int_as_float(0x7f800000)
#define DEADU 0xffffffffu

// scratch (no allocations allowed -> __device__ globals)
__device__ float g_costT[BB * MM * QQ];                 // 14.7 MB [b][m][q]
__device__ unsigned long long g_part1[BB * NT * MM];    // per-tile column min
__device__ unsigned long long g_part2[BB * NT * MM];    // per-tile column 2nd min
__device__ float g_lse[BB * QQ];
__device__ float g_acc[3];
__device__ unsigned g_done;

// monotone float->uint mapping (preserves < ordering)
__device__ __forceinline__ unsigned ford(float f) {
    unsigned u = __float_as_uint(f);
    return u ^ ((u >> 31) ? 0xffffffffu : 0x80000000u);
}

// ---------------- kernel A: softmax + cost tile + per-tile column top-2 --------
// grid (NT, B), block 128.
__global__ void __launch_bounds__(128) k_costT(
    const float* __restrict__ logits,
    const float* __restrict__ pboxes,
    const float* __restrict__ tboxes,
    const float* __restrict__ sizes,
    const int*   __restrict__ labels) {
    int b = blockIdx.y, tid = threadIdx.x;
    int q0 = blockIdx.x * 128;
    int q = q0 + tid;
    __shared__ float sprob[128 * KP1];       // 41.5 KB
    __shared__ float tn0[MM], tn1[MM], tn2[MM], tn3[MM], tc[MM], ts[MM];
    __shared__ int   tl[MM];
    __shared__ float pq0[128], pq1[128], pq2[128], pq3[128], pqc[128], pqs[128];

    if (b == 0 && blockIdx.x == 0 && tid < 4) {
        if (tid < 3) g_acc[tid] = 0.f; else g_done = 0u;
    }

    float H = sizes[b * 2 + 0], W = sizes[b * 2 + 1];
    {   // tid doubles as target index m
        const float* tb = tboxes + ((size_t)b * MM + tid) * 5;
        tn0[tid] = tb[0] / W; tn1[tid] = tb[1] / H;
        tn2[tid] = tb[2] / W; tn3[tid] = tb[3] / H;
        float sn, cs; sincosf(tb[4], &sn, &cs);
        tc[tid] = cs; ts[tid] = sn;
        tl[tid] = labels[b * MM + tid];
    }
    int nrow = min(128, QQ - q0);
    int tot = nrow * KP1;
    const float* lg0 = logits + ((size_t)b * QQ + q0) * KP1;
    for (int i = tid; i < tot; i += 128) sprob[i] = lg0[i];
    __syncthreads();

    bool valid = q < QQ;
    if (valid) {
        float* r = sprob + tid * KP1;        // stride 81: bank-conflict-free
        float mx = -FLT_MAX;
#pragma unroll 9
        for (int k = 0; k < KP1; k++) mx = fmaxf(mx, r[k]);
        float s = 0.f;
#pragma unroll 9
        for (int k = 0; k < KP1; k++) { float e = __expf(r[k] - mx); r[k] = e; s += e; }
        float inv = 1.f / s;
#pragma unroll 9
        for (int k = 0; k < KP1; k++) r[k] *= inv;
        g_lse[b * QQ + q] = mx + __logf(s);
        const float* pb = pboxes + ((size_t)b * QQ + q) * 5;
        float sn, cs; sincosf(pb[4], &sn, &cs);
        pq0[tid] = pb[0]; pq1[tid] = pb[1]; pq2[tid] = pb[2]; pq3[tid] = pb[3];
        pqc[tid] = cs; pqs[tid] = sn;
    }
    __syncthreads();

    // ---- write transposed cost tile (thread = q, coalesced along q) ----
    if (valid) {
        float p0 = pq0[tid], p1 = pq1[tid], p2 = pq2[tid], p3 = pq3[tid];
        float pc = pqc[tid], psn = pqs[tid];
        const float* r = sprob + tid * KP1;
        float* outb = g_costT + (size_t)b * MM * QQ + q;
#pragma unroll 4
        for (int m = 0; m < MM; m++) {
            float prob = r[tl[m]];
            float l1 = fabsf(p0 - tn0[m]) + fabsf(p1 - tn1[m]) +
                       fabsf(p2 - tn2[m]) + fabsf(p3 - tn3[m]);
            float cosd = pc * tc[m] + psn * ts[m];
            outb[(size_t)m * QQ] = -2.f * prob + 5.f * l1 + 2.f * (1.f - cosd);
        }
    }

    // ---- per-tile column top-2 (thread = m, recompute from smem) ----
    {
        int m = tid;
        float t0 = tn0[m], t1 = tn1[m], t2 = tn2[m], t3 = tn3[m];
        float tcc = tc[m], tss = ts[m];
        int lab = tl[m];
        float bv1 = INFF, bv2 = INFF; int bq1 = 0x3ff, bq2 = 0x3ff;
        for (int j = 0; j < nrow; j++) {
            float prob = sprob[j * KP1 + lab];
            float l1 = fabsf(pq0[j] - t0) + fabsf(pq1[j] - t1) +
                       fabsf(pq2[j] - t2) + fabsf(pq3[j] - t3);
            float cosd = pqc[j] * tcc + pqs[j] * tss;
            float v = -2.f * prob + 5.f * l1 + 2.f * (1.f - cosd);
            if (v < bv1) { bv2 = bv1; bq2 = bq1; bv1 = v; bq1 = q0 + j; }
            else if (v < bv2) { bv2 = v; bq2 = q0 + j; }
        }
        size_t idx = ((size_t)b * NT + blockIdx.x) * MM + m;
        g_part1[idx] = ((unsigned long long)ford(bv1) << 32) | (unsigned)bq1;
        g_part2[idx] = ((unsigned long long)ford(bv2) << 32) | (unsigned)bq2;
    }
}

// ---------------- kernel B: match (warp0, reg state + 2nd-min backup) + loss ---
__global__ void __launch_bounds__(256, 1) k_match_loss(
    const float* __restrict__ logits,
    const float* __restrict__ pboxes,
    const float* __restrict__ tboxes,
    const float* __restrict__ sizes,
    const int*   __restrict__ labels,
    float* __restrict__ out) {
    int b = blockIdx.x, tid = threadIdx.x;
    int lane = tid & 31, wid = tid >> 5;
    __shared__ unsigned cum[MM], cum2[MM];
    __shared__ int      carg[MM], carg2[MM];
    __shared__ float    rmask[1024];   // 0 = free row, +INF = used (padded)
    __shared__ short    sq[MM], sm[MM];
    __shared__ int      mlab[QQ];
    __shared__ float    buf[256];
    const float* C = g_costT + (size_t)b * MM * QQ;

    for (int q = tid; q < 1024; q += 256) rmask[q] = 0.f;

    // ---- init from per-tile partials: merge 8 (min1,min2) pairs per column ----
    if (tid < MM) {
        const unsigned long long* p1 = g_part1 + (size_t)b * NT * MM + tid;
        const unsigned long long* p2 = g_part2 + (size_t)b * NT * MM + tid;
        unsigned long long b1 = ~0ull, b2 = ~0ull;
#pragma unroll
        for (int t = 0; t < NT; t++) {
            unsigned long long a = p1[t * MM];
            unsigned long long c = p2[t * MM];
            if (a < b1) { b2 = (b1 < c) ? b1 : c; b1 = a; }
            else if (a < b2) { b2 = a; }
        }
        cum[tid]  = (unsigned)(b1 >> 32); carg[tid]  = (int)(unsigned)(b1 & 0xffffffffu);
        cum2[tid] = (unsigned)(b2 >> 32); carg2[tid] = (int)(unsigned)(b2 & 0xffffffffu);
    }
    __syncthreads();

    // ---- matching loop: warp0 only, state in registers ----
    if (wid == 0) {
        unsigned u[4], u2[4]; int qa[4], qa2[4];
#pragma unroll
        for (int g = 0; g < 4; g++) {
            u[g]  = cum[lane + 32 * g];  qa[g]  = carg[lane + 32 * g];
            u2[g] = cum2[lane + 32 * g]; qa2[g] = carg2[lane + 32 * g] & 1023;
        }

        for (int it = 0; it < MM; it++) {
            // global argmin over 128 (value, q, m) keys
            unsigned long long key = ~0ull;
#pragma unroll
            for (int g = 0; g < 4; g++) {
                unsigned long long k2 = ((unsigned long long)u[g] << 17)
                                      | ((unsigned)qa[g] << 7) | (unsigned)(lane + 32 * g);
                if (k2 < key) key = k2;
            }
            unsigned hi = (unsigned)(key >> 17);
            unsigned himin = __reduce_min_sync(0xffffffffu, hi);
            unsigned lo = (hi == himin) ? (unsigned)(key & 0x1ffffu) : 0xffffffffu;
            unsigned lomin = __reduce_min_sync(0xffffffffu, lo);
            int qs = (int)(lomin >> 7);
            int ms = (int)(lomin & 127u);

            if (lane == 0) { sq[it] = (short)qs; sm[it] = (short)ms; rmask[qs] = INFF; }
            if (lane == (ms & 31)) { u[ms >> 5] = DEADU; qa[ms >> 5] = 0x3ff; }
            __syncwarp();
            if (it == MM - 1) break;

            // columns whose cached argmin row was consumed: backup or rescan
#pragma unroll
            for (int g = 0; g < 4; g++) {
                bool hit = (qa[g] == qs) && (u[g] != DEADU);
                bool fb = false;
                if (hit && u2[g] != DEADU) {
                    int qb = qa2[g];
                    if (rmask[qb] == 0.f) {     // exact: nothing < min2 except min1
                        u[g] = u2[g]; qa[g] = qb; u2[g] = DEADU; fb = true;
                    }
                }
                unsigned bal = __ballot_sync(0xffffffffu, hit && !fb);
                while (bal) {
                    int c = __ffs(bal) - 1; bal &= bal - 1;
                    int mr = c + 32 * g;
                    const float* col = C + (size_t)mr * QQ;
                    float nv = INFF; int nq = 0x3ff;
#pragma unroll 7
                    for (int j = 0; j < 28; j++) {
                        int q2 = lane + 32 * j;
                        float v = col[q2] + rmask[q2];
                        if (v < nv) { nv = v; nq = q2; }
                    }
                    { int q2 = lane + 896; if (q2 < QQ) { float v = col[q2] + rmask[q2]; if (v < nv) { nv = v; nq = q2; } } }
                    unsigned uu = ford(nv);
                    unsigned um = __reduce_min_sync(0xffffffffu, uu);
                    unsigned qq = (uu == um) ? (unsigned)nq : 0xffffffffu;
                    unsigned qmn = __reduce_min_sync(0xffffffffu, qq);
                    if (lane == c) { u[g] = um; qa[g] = (int)qmn; u2[g] = DEADU; }
                    __syncwarp();
                }
            }
        }
    }
    __syncthreads();

    // ---- fused per-image losses (all 256 threads) ----
    for (int q = tid; q < QQ; q += 256) mlab[q] = -1;
    __syncthreads();
    if (tid < MM) mlab[sq[tid]] = labels[b * MM + sm[tid]];
    __syncthreads();

    float num = 0.f;
    for (int q = tid; q < QQ; q += 256) {
        int c = mlab[q];
        float w;
        if (c < 0) { c = KC; w = 0.1f; } else w = 1.f;
        int row = b * QQ + q;
        num += w * (g_lse[row] - logits[(size_t)row * KP1 + c]);
    }

    float sb = 0.f, sa = 0.f;
    if (tid < MM) {
        int q = sq[tid], m = sm[tid];
        float H = sizes[b * 2 + 0], W = sizes[b * 2 + 1];
        const float* pb = pboxes + ((size_t)b * QQ + q) * 5;
        const float* tb = tboxes + ((size_t)b * MM + m) * 5;
        sb = fabsf(pb[0] - tb[0] / W) + fabsf(pb[1] - tb[1] / H) +
             fabsf(pb[2] - tb[2] / W) + fabsf(pb[3] - tb[3] / H);
        sa = 1.f - cosf(pb[4] - tb[4]);
    }

    buf[tid] = num; __syncthreads();
    for (int s = 128; s > 0; s >>= 1) { if (tid < s) buf[tid] += buf[tid + s]; __syncthreads(); }
    float numt = buf[0]; __syncthreads();
    buf[tid] = sb; __syncthreads();
    for (int s = 128; s > 0; s >>= 1) { if (tid < s) buf[tid] += buf[tid + s]; __syncthreads(); }
    float sbt = buf[0]; __syncthreads();
    buf[tid] = sa; __syncthreads();
    for (int s = 128; s > 0; s >>= 1) { if (tid < s) buf[tid] += buf[tid + s]; __syncthreads(); }
    float sat = buf[0];

    if (tid == 0) {
        atomicAdd(&g_acc[0], numt);
        atomicAdd(&g_acc[1], sbt);
        atomicAdd(&g_acc[2], sat);
        __threadfence();
        unsigned done = atomicAdd(&g_done, 1u);
        if (done == BB - 1) {
            const float den = 0.1f * (QQ - MM) + (float)MM;   // 205.2 per image
            float lc = g_acc[0] / (den * BB);
            float lb = g_acc[1] * 5.f / (float)(MM * 4 * BB);
            float la = g_acc[2] * 2.f / (float)(MM * BB);
            out[0] = lc;
            out[1] = lb;
            out[2] = la;
            out[3] = lc + lb + la;
        }
    }
}

extern "C" void kernel_launch(void* const* d_in, const int* in_sizes, int n_in,
                              void* d_out, int out_size) {
    const float* logits = (const float*)d_in[0];   // [B,Q,81]
    const float* pboxes = (const float*)d_in[1];   // [B,Q,5]
    const float* tboxes = (const float*)d_in[2];   // [B,M,5]
    const float* sizes  = (const float*)d_in[3];   // [B,2]
    const int*   labels = (const int*)d_in[4];     // [B,M]
    float* out = (float*)d_out;

    dim3 gc(NT, BB);
    k_costT<<<gc, 128>>>(logits, pboxes, tboxes, sizes, labels);
    k_match_loss<<<BB, 256>>>(logits, pboxes, tboxes, sizes, labels, out);
}